// round 7
// baseline (speedup 1.0000x reference)
#include <cuda_runtime.h>

#define N_TOK   8192
#define E_EXP   8
#define DIM     2048
#define OUT_ROWS (N_TOK * 2)              // 16384
#define TAGS_OFF ((size_t)OUT_ROWS * DIM) // 33554432
#define CNT_OFF  (TAGS_OFF + OUT_ROWS)
#define NBLK    1024                      // persistent blocks, 8 tokens each
#define TPB     8                         // tokens per block

// scratch (no device allocs allowed)
__device__ unsigned long long g_bcnt_lo[NBLK];
__device__ unsigned long long g_bcnt_hi[NBLK];
__device__ unsigned int       g_sync;     // monotonic ticket barrier (replay-safe)

// 4 expert-counters in 16-bit fields of a u64
__device__ __forceinline__ unsigned long long spread4(unsigned int m4) {
    return (unsigned long long)(m4 & 1)
         | ((unsigned long long)((m4 >> 1) & 1) << 16)
         | ((unsigned long long)((m4 >> 2) & 1) << 32)
         | ((unsigned long long)((m4 >> 3) & 1) << 48);
}
__device__ __forceinline__ int fld(unsigned long long v, int e) {
    return (int)((v >> (16 * e)) & 0xFFFF);
}

__global__ __launch_bounds__(256, 8) void fused_kernel(
    const float4* __restrict__ gates4,
    const float4* __restrict__ in_flow,
    float4* __restrict__ out4,
    float* __restrict__ out)
{
    __shared__ unsigned int       s_mask[TPB];
    __shared__ int2               s_dst[TPB];
    __shared__ unsigned long long s_red[8][4];   // per-warp partials
    __shared__ unsigned long long s_bc[4];       // tot_lo, tot_hi, pre_lo, pre_hi

    const int b = blockIdx.x;
    const int t = threadIdx.x;
    const int lane = t & 31, w = t >> 5;

    // ───── Phase 1: route this block's 8 tokens (threads 0..7) ─────
    unsigned long long lo = 0ull, hi = 0ull;
    if (t < TPB) {
        const int n = b * TPB + t;
        const float4 a  = __ldg(gates4 + (size_t)n * 2);
        const float4 b4 = __ldg(gates4 + (size_t)n * 2 + 1);
        float g[E_EXP] = {a.x, a.y, a.z, a.w, b4.x, b4.y, b4.z, b4.w};

        int e1 = 0; float v1 = g[0];
        #pragma unroll
        for (int e = 1; e < E_EXP; e++) if (g[e] > v1) { v1 = g[e]; e1 = e; }
        int e2 = (e1 == 0) ? 1 : 0; float v2 = g[e2];
        #pragma unroll
        for (int e = 0; e < E_EXP; e++)
            if (e != e1 && g[e] > v2) { v2 = g[e]; e2 = e; }
        const unsigned int mb = (1u << e1) | (1u << e2);
        s_mask[t] = mb;
        lo = spread4(mb & 0xF);
        hi = spread4(mb >> 4);
    }
    // reduce the 8 lanes' packed counts within warp 0
    if (w == 0) {
        #pragma unroll
        for (int off = 4; off > 0; off >>= 1) {
            lo += __shfl_down_sync(0xFFFFFFFFu, lo, off);
            hi += __shfl_down_sync(0xFFFFFFFFu, hi, off);
        }
        if (lane == 0) {
            g_bcnt_lo[b] = lo;
            g_bcnt_hi[b] = hi;
        }
    }

    // ───── device-wide ticket barrier (all 1024 blocks resident) ─────
    __syncthreads();
    if (t == 0) {
        __threadfence();
        const unsigned int ticket = atomicAdd(&g_sync, 1u);
        const unsigned int target = (ticket / NBLK + 1u) * NBLK;
        volatile unsigned int* sy = &g_sync;
        while (*sy < target) { }
        __threadfence();
    }
    __syncthreads();

    // ───── Phase 2: global totals + prefix over earlier blocks ─────
    unsigned long long tlo = 0ull, thi = 0ull, plo = 0ull, phi = 0ull;
    #pragma unroll
    for (int i = t; i < NBLK; i += 256) {
        const unsigned long long l = g_bcnt_lo[i];
        const unsigned long long h = g_bcnt_hi[i];
        tlo += l; thi += h;
        if (i < b) { plo += l; phi += h; }
    }
    #pragma unroll
    for (int off = 16; off > 0; off >>= 1) {
        tlo += __shfl_down_sync(0xFFFFFFFFu, tlo, off);
        thi += __shfl_down_sync(0xFFFFFFFFu, thi, off);
        plo += __shfl_down_sync(0xFFFFFFFFu, plo, off);
        phi += __shfl_down_sync(0xFFFFFFFFu, phi, off);
    }
    if (lane == 0) {
        s_red[w][0] = tlo; s_red[w][1] = thi;
        s_red[w][2] = plo; s_red[w][3] = phi;
    }
    __syncthreads();

    if (t == 0) {
        unsigned long long a0 = 0, a1 = 0, a2 = 0, a3 = 0;
        #pragma unroll
        for (int i = 0; i < 8; i++) {
            a0 += s_red[i][0]; a1 += s_red[i][1];
            a2 += s_red[i][2]; a3 += s_red[i][3];
        }
        // expert totals and bases
        int cnt[E_EXP], ebase[E_EXP];
        #pragma unroll
        for (int e = 0; e < 4; e++) { cnt[e] = fld(a0, e); cnt[e + 4] = fld(a1, e); }
        int acc = 0;
        #pragma unroll
        for (int e = 0; e < E_EXP; e++) { ebase[e] = acc; acc += cnt[e]; }

        // running write cursor per expert = ebase + prefix from earlier blocks
        int run[E_EXP];
        #pragma unroll
        for (int e = 0; e < 4; e++) {
            run[e]     = ebase[e]     + fld(a2, e);
            run[e + 4] = ebase[e + 4] + fld(a3, e);
        }
        // serial stable scan over this block's 8 tokens
        #pragma unroll
        for (int i = 0; i < TPB; i++) {
            const unsigned int mb = s_mask[i];
            int d0 = -1, d1 = -1;
            #pragma unroll
            for (int e = 0; e < E_EXP; e++) {
                if ((mb >> e) & 1u) {
                    if (d0 < 0) d0 = run[e]; else d1 = run[e];
                    run[e]++;
                }
            }
            s_dst[i] = make_int2(d0, d1);
        }
        if (b == 0) {
            #pragma unroll
            for (int e = 0; e < E_EXP; e++) out[CNT_OFF + e] = (float)cnt[e];
        }
    }
    __syncthreads();

    // ───── Phase 3: gather this block's 8 rows, write each twice ─────
    #pragma unroll
    for (int r = 0; r < TPB; r++) {
        const int n = b * TPB + r;
        const int2 d = s_dst[r];

        const float4* __restrict__ src = in_flow + (size_t)n * (DIM / 4);
        const float4 v0 = __ldg(src + t);
        const float4 v1 = __ldg(src + t + 256);

        float4* __restrict__ dst0 = out4 + (size_t)d.x * (DIM / 4);
        float4* __restrict__ dst1 = out4 + (size_t)d.y * (DIM / 4);
        __stcs(dst0 + t,       v0);
        __stcs(dst0 + t + 256, v1);
        __stcs(dst1 + t,       v0);
        __stcs(dst1 + t + 256, v1);

        if (t == 0) {
            out[TAGS_OFF + d.x] = (float)n;
            out[TAGS_OFF + d.y] = (float)n;
        }
    }
}

extern "C" void kernel_launch(void* const* d_in, const int* in_sizes, int n_in,
                              void* d_out, int out_size)
{
    const float* in_flow = (const float*)d_in[0];   // (8192, 2048) f32
    const float* gates   = (const float*)d_in[1];   // (8192, 8)    f32
    float* out = (float*)d_out;

    fused_kernel<<<NBLK, 256>>>((const float4*)gates, (const float4*)in_flow,
                                (float4*)out, out);
}